// round 16
// baseline (speedup 1.0000x reference)
#include <cuda_runtime.h>
#include <cuda_bf16.h>
#include <math.h>
#include <stdint.h>

#define D_DIM 256
#define MAXB  64
#define MAXK  4096
#define TOPK_NT 1024
#define SEG   20
#define NSTRIPE 8

#define TBL     4096              // interpolation table size
#define TGM_MT  32                // grid rows per table-GEMM block
#define TGM_BLOCKS (TBL / TGM_MT) // 128
#define KC      64                // K elements per chunk
#define NCHUNK  (D_DIM / KC)      // 4
// dynamic smem (table-GEMM path): A hi/lo then B hi/lo, 128B rows, XOR swizzle
#define A_HALF  (TGM_MT * 128)    // 4096 B
#define OFF_B   (2 * A_HALF)      // 8192
#define B_HALF  (D_DIM * 128)     // 32768 B
#define DYN_BYTES (2 * A_HALF + 2 * B_HALF)   // 73728

// scratch (no cudaMalloc allowed)
__device__ int2  g_selv[MAXB * MAXK];         // {gene_idx, expr_bits}
__device__ int   g_cnt[MAXB];
__device__ float g_tbl[TBL * D_DIM];          // F(x_i) + b2, 4 MB

// ---------------- mma / ldmatrix helpers ----------------
__device__ __forceinline__ void mma_bf16(float* c, const uint32_t* a, const uint32_t* b) {
    asm volatile(
        "mma.sync.aligned.m16n8k16.row.col.f32.bf16.bf16.f32 "
        "{%0,%1,%2,%3}, {%4,%5,%6,%7}, {%8,%9}, {%0,%1,%2,%3};"
        : "+f"(c[0]), "+f"(c[1]), "+f"(c[2]), "+f"(c[3])
        : "r"(a[0]), "r"(a[1]), "r"(a[2]), "r"(a[3]), "r"(b[0]), "r"(b[1]));
}
__device__ __forceinline__ void ldm_x4(uint32_t* r, const char* p) {
    uint32_t a = (uint32_t)__cvta_generic_to_shared(p);
    asm volatile("ldmatrix.sync.aligned.m8n8.x4.shared.b16 {%0,%1,%2,%3}, [%4];"
                 : "=r"(r[0]), "=r"(r[1]), "=r"(r[2]), "=r"(r[3]) : "r"(a));
}

// ---------------- block scan (exclusive) ----------------
__device__ __forceinline__ void block_scan(int v, int& excl, int& total) {
    const int tid  = threadIdx.x;
    const int lane = tid & 31, wrp = tid >> 5;
    const int nw   = blockDim.x >> 5;
    __shared__ int wsum[32];
    int inc = v;
#pragma unroll
    for (int o = 1; o < 32; o <<= 1) {
        int n = __shfl_up_sync(0xFFFFFFFFu, inc, o);
        if (lane >= o) inc += n;
    }
    if (lane == 31) wsum[wrp] = inc;
    __syncthreads();
    if (wrp == 0) {
        int w = (lane < nw) ? wsum[lane] : 0;
#pragma unroll
        for (int o = 1; o < 32; o <<= 1) {
            int n = __shfl_up_sync(0xFFFFFFFFu, w, o);
            if (lane >= o) w += n;
        }
        wsum[lane] = w;
    }
    __syncthreads();
    int woff = wrp ? wsum[wrp - 1] : 0;
    excl  = woff + inc - v;
    total = wsum[nw - 1];
    __syncthreads();
}

__device__ __forceinline__ float gelu_exact(float z) {
    return 0.5f * z * (1.0f + erff(z * 0.70710678118654752f));
}
__device__ __forceinline__ void split_bf16(float v, unsigned short& h, unsigned short& l) {
    __nv_bfloat16 hb = __float2bfloat16(v);
    __nv_bfloat16 lb = __float2bfloat16(v - __bfloat162float(hb));
    h = *(unsigned short*)&hb;
    l = *(unsigned short*)&lb;
}

// ================= fused kernel: topk (blocks 0..B-1) + table GEMM (blocks B..B+127) =================
__global__ __launch_bounds__(TOPK_NT)
void fused_kernel(const float* __restrict__ expr,
                  const float* __restrict__ w1,
                  const float* __restrict__ b1,
                  const float* __restrict__ w2,
                  const float* __restrict__ b2,
                  const float* __restrict__ cls,
                  float* __restrict__ out,
                  int B, int G, int K, int hasMask) {
    const int tid = threadIdx.x;

    if (blockIdx.x >= (unsigned)B) {
        // ================== table GEMM path ==================
        extern __shared__ char dyn[];
        __shared__ float sw1[D_DIM], sb1[D_DIM], sb2g[D_DIM];

        const int bid  = blockIdx.x - B;
        const int wid  = tid >> 5, lane = tid & 31;
        const int wm   = wid >> 4;            // 0..1
        const int wn   = wid & 15;            // 0..15
        const int gr   = lane >> 2;           // 0..7
        const int cq   = lane & 3;            // 0..3

        if (tid < D_DIM) { sw1[tid] = w1[tid]; sb1[tid] = b1[tid]; sb2g[tid] = b2[tid]; }
        __syncthreads();

        float acc[2][4];
#pragma unroll
        for (int ni = 0; ni < 2; ++ni)
#pragma unroll
            for (int j = 0; j < 4; ++j) acc[ni][j] = 0.0f;

        // fill constants
        const int at  = tid >> 5;             // 0..31 grid row (A fill)
        const int k2  = (lane) * 2;           // 2 k-elems per thread per chunk
        const float xg = (float)(bid * TGM_MT + at) * (1.0f / (float)(TBL - 1));
        const int bn  = tid >> 2;             // 0..255 output row (B fill)
        const int bkq = (tid & 3) * 16;       // 16 k-elems per thread per chunk

        // ldmatrix constants
        const int a_r   = (lane & 7) + ((lane >> 3) & 1) * 8;
        const uint32_t a_kb4 = (uint32_t)((lane >> 4) << 4);
        const int b_r   = (lane & 7) + ((lane >> 4) & 1) * 8;
        const uint32_t b_kb4 = (uint32_t)(((lane >> 3) & 1) << 4);
        const uint32_t xo = (uint32_t)((lane & 7) << 4);

        char* const Ah = dyn;
        char* const Al = dyn + A_HALF;
        char* const Bh = dyn + OFF_B;
        char* const Bl = dyn + OFF_B + B_HALF;

        for (int c = 0; c < NCHUNK; ++c) {
            const int d0 = c * KC;
            // --- A fill: h = gelu(xg*w1+b1), hi/lo, 2 elems/thread ---
            {
                int d = d0 + k2;
                float h0 = gelu_exact(fmaf(xg, sw1[d],     sb1[d]));
                float h1 = gelu_exact(fmaf(xg, sw1[d + 1], sb1[d + 1]));
                unsigned short h0h, h0l, h1h, h1l;
                split_bf16(h0, h0h, h0l);
                split_bf16(h1, h1h, h1l);
                uint32_t hp = (uint32_t)h0h | ((uint32_t)h1h << 16);
                uint32_t lp = (uint32_t)h0l | ((uint32_t)h1l << 16);
                uint32_t boff = (uint32_t)(at * 128) + (((uint32_t)(k2 * 2)) ^ ((uint32_t)((at & 7) << 4)));
                *(uint32_t*)(Ah + boff) = hp;
                *(uint32_t*)(Al + boff) = lp;
            }
            // --- B fill: w2 fp32 -> split hi/lo, 16 elems/thread ---
            {
                const float* src = &w2[(size_t)bn * D_DIM + d0 + bkq];
                uint32_t rowbase = (uint32_t)(bn * 128);
                uint32_t xorn = (uint32_t)((bn & 7) << 4);
#pragma unroll
                for (int grp = 0; grp < 2; ++grp) {
                    float4 v0 = *(const float4*)(src + grp * 8);
                    float4 v1 = *(const float4*)(src + grp * 8 + 4);
                    float vv[8] = {v0.x, v0.y, v0.z, v0.w, v1.x, v1.y, v1.z, v1.w};
                    unsigned short hs[8], ls[8];
#pragma unroll
                    for (int j = 0; j < 8; ++j) split_bf16(vv[j], hs[j], ls[j]);
                    uint4 hq, lq;
                    hq.x = (uint32_t)hs[0] | ((uint32_t)hs[1] << 16);
                    hq.y = (uint32_t)hs[2] | ((uint32_t)hs[3] << 16);
                    hq.z = (uint32_t)hs[4] | ((uint32_t)hs[5] << 16);
                    hq.w = (uint32_t)hs[6] | ((uint32_t)hs[7] << 16);
                    lq.x = (uint32_t)ls[0] | ((uint32_t)ls[1] << 16);
                    lq.y = (uint32_t)ls[2] | ((uint32_t)ls[3] << 16);
                    lq.z = (uint32_t)ls[4] | ((uint32_t)ls[5] << 16);
                    lq.w = (uint32_t)ls[6] | ((uint32_t)ls[7] << 16);
                    uint32_t boff = rowbase + (((uint32_t)(bkq * 2 + grp * 16)) ^ xorn);
                    *(uint4*)(Bh + boff) = hq;
                    *(uint4*)(Bl + boff) = lq;
                }
            }
            __syncthreads();

            // --- mainloop: 4 k-steps of 16 ---
#pragma unroll
            for (int ks = 0; ks < 4; ++ks) {
                const uint32_t kb2 = (uint32_t)(ks * 32);
                const uint32_t aks = (kb2 | a_kb4) ^ xo;
                const uint32_t bks = (kb2 | b_kb4) ^ xo;
                uint32_t ahi[4], alo[4], bh[4], bl[4];
                const uint32_t aoff = (uint32_t)((wm * 16 + a_r) * 128) + aks;
                ldm_x4(ahi, Ah + aoff);
                ldm_x4(alo, Al + aoff);
                const uint32_t boff = (uint32_t)((wn * 16 + b_r) * 128) + bks;
                ldm_x4(bh, Bh + boff);
                ldm_x4(bl, Bl + boff);
#pragma unroll
                for (int half = 0; half < 2; ++half) {
                    const uint32_t* bhv = bh + half * 2;
                    const uint32_t* blv = bl + half * 2;
                    mma_bf16(acc[half], ahi, bhv);
                    mma_bf16(acc[half], ahi, blv);
                    mma_bf16(acc[half], alo, bhv);
                }
            }
            __syncthreads();
        }

        // epilogue: table row = F(xg) + b2
#pragma unroll
        for (int h8 = 0; h8 < 2; ++h8) {
            int row = bid * TGM_MT + wm * 16 + gr + h8 * 8;
#pragma unroll
            for (int ni = 0; ni < 2; ++ni) {
                int e = wn * 16 + ni * 8 + 2 * cq;
                float2 v;
                v.x = acc[ni][h8 * 2 + 0] + sb2g[e];
                v.y = acc[ni][h8 * 2 + 1] + sb2g[e + 1];
                *(float2*)(&g_tbl[(size_t)row * D_DIM + e]) = v;
            }
        }
        return;
    }

    // ================== top-k path ==================
    const int b = blockIdx.x;
    const float* __restrict__ row = expr + (size_t)b * G;

    __shared__ unsigned int hist[256 * NSTRIPE];   // striped: hist[dig*8 + stripe]
    __shared__ unsigned int s_prefix;
    __shared__ int s_remaining;

    const int base = tid * SEG;
    const int stripe = tid & (NSTRIPE - 1);
    unsigned keys[SEG];
    if (base + SEG <= G) {
#pragma unroll
        for (int i = 0; i < SEG; i += 4) {
            float4 v = *(const float4*)(&row[base + i]);
            keys[i + 0] = __float_as_uint(v.x);
            keys[i + 1] = __float_as_uint(v.y);
            keys[i + 2] = __float_as_uint(v.z);
            keys[i + 3] = __float_as_uint(v.w);
        }
    } else {
#pragma unroll
        for (int i = 0; i < SEG; ++i)
            keys[i] = (base + i < G) ? __float_as_uint(row[base + i]) : 0u;
    }

    if (tid == 0) { s_prefix = 0u; s_remaining = K; }
    __syncthreads();

#pragma unroll
    for (int pass = 0; pass < 4; ++pass) {
        const int shift = 24 - 8 * pass;
        const unsigned maskHigh = (pass == 0) ? 0u : (0xFFFFFFFFu << (shift + 8));
#pragma unroll
        for (int i = 0; i < (256 * NSTRIPE) / TOPK_NT; ++i)
            hist[i * TOPK_NT + tid] = 0u;
        __syncthreads();
        const unsigned prefix = s_prefix;
        const int rem = s_remaining;
#pragma unroll
        for (int i = 0; i < SEG; ++i) {
            unsigned key = keys[i];
            if ((key & maskHigh) == prefix)
                atomicAdd(&hist[((key >> shift) & 0xFFu) * NSTRIPE + stripe], 1u);
        }
        __syncthreads();
        int v = 0;
        if (tid < 256) {
            int h0 = (255 - tid) * NSTRIPE;
#pragma unroll
            for (int s = 0; s < NSTRIPE; ++s) v += (int)hist[h0 + s];
        }
        int excl, total;
        block_scan(v, excl, total);
        int incl = excl + v;
        if (tid < 256 && incl >= rem && excl < rem) {
            s_prefix    = prefix | ((unsigned)(255 - tid) << shift);
            s_remaining = rem - excl;
        }
        __syncthreads();
    }
    const unsigned pivot = s_prefix;
    const int r = s_remaining;

    int n_gt = 0, n_eq = 0;
#pragma unroll
    for (int i = 0; i < SEG; ++i) {
        n_gt += (keys[i] > pivot);
        n_eq += (keys[i] == pivot);
    }
    int eq_base, eq_tot;
    block_scan(n_eq, eq_base, eq_tot);
    int eq_keep = 0;
    if (pivot > 0u) {
        int take = r - eq_base;
        eq_keep = take < 0 ? 0 : (take > n_eq ? n_eq : take);
    }
    int n_keep = n_gt + eq_keep;
    int out_base, out_tot;
    block_scan(n_keep, out_base, out_tot);

    int pos = out_base, erank = eq_base;
    int2* __restrict__ sel = g_selv + b * MAXK;
#pragma unroll
    for (int i = 0; i < SEG; ++i) {
        unsigned key = keys[i];
        if (key > pivot) {
            sel[pos++] = make_int2(base + i, (int)key);
        } else if (key == pivot) {
            if (pivot > 0u && erank < r) sel[pos++] = make_int2(base + i, (int)key);
            ++erank;
        }
    }
    const int cnt = (out_tot < K) ? out_tot : K;
    if (tid == 0) g_cnt[b] = cnt;

    // ---- fused cls row + mask epilogue ----
    const size_t rowsz = (size_t)(K + 1) * D_DIM;
    float* orow = out + (size_t)b * rowsz;
    if (tid < D_DIM) __stcs(&orow[tid], cls[tid]);
    if (hasMask) {
        float* mask = out + (size_t)B * rowsz + (size_t)b * (K + 1);
        for (int j = tid; j < K + 1; j += TOPK_NT)
            __stcs(&mask[j], (j == 0 || (j - 1) < cnt) ? 1.0f : 0.0f);
    }
}

// ================= interp/gather kernel (warp-per-token) =================
// 256 threads = 8 warps = 8 tokens per block. Block-level metadata prefetch:
// one coalesced 64B load for the 8 tokens' {gene, expr_bits} pairs.
__global__ __launch_bounds__(256)
void interp_kernel(const float* __restrict__ gene_emb,
                   float* __restrict__ out,
                   int B, int G, int K) {
    __shared__ int2 smeta[8];
    __shared__ int  scnt;

    const int tid  = threadIdx.x;
    const int wid  = tid >> 5;
    const int lane = tid & 31;
    const int tkn0 = blockIdx.x * 8;
    const int b    = tkn0 / K;           // K % 8 == 0 -> same b for whole block
    const int k0   = tkn0 - b * K;

    if (tid < 8) smeta[tid] = g_selv[b * MAXK + k0 + tid];   // one 64B transaction
    if (tid == 8) scnt = g_cnt[b];
    __syncthreads();

    const int k = k0 + wid;
    const int2 gv = smeta[wid];
    const int cnt = scnt;

    const size_t rowoff = ((size_t)b * (K + 1) + (k + 1)) * D_DIM;
    float4* __restrict__ orow = (float4*)(out + rowoff);

    if (k < cnt) {
        const int gi = gv.x;
        float x = __int_as_float(gv.y);
        float u = x * (float)(TBL - 1);
        int i0 = (int)u;
        if (i0 < 0) i0 = 0;
        if (i0 > TBL - 2) i0 = TBL - 2;
        float f = u - (float)i0;

        const float4* __restrict__ T0 = (const float4*)(&g_tbl[(size_t)i0 * D_DIM]);
        const float4* __restrict__ T1 = (const float4*)(&g_tbl[(size_t)(i0 + 1) * D_DIM]);
        const float4* __restrict__ GE = (const float4*)(&gene_emb[(size_t)gi * D_DIM]);

        // issue all 6 loads before consuming (MLP=6)
        float4 t0a = T0[lane],      t0b = T0[lane + 32];
        float4 t1a = T1[lane],      t1b = T1[lane + 32];
        float4 gea = GE[lane],      geb = GE[lane + 32];

        float4 va, vb;
        va.x = fmaf(t1a.x - t0a.x, f, t0a.x) + gea.x;
        va.y = fmaf(t1a.y - t0a.y, f, t0a.y) + gea.y;
        va.z = fmaf(t1a.z - t0a.z, f, t0a.z) + gea.z;
        va.w = fmaf(t1a.w - t0a.w, f, t0a.w) + gea.w;
        vb.x = fmaf(t1b.x - t0b.x, f, t0b.x) + geb.x;
        vb.y = fmaf(t1b.y - t0b.y, f, t0b.y) + geb.y;
        vb.z = fmaf(t1b.z - t0b.z, f, t0b.z) + geb.z;
        vb.w = fmaf(t1b.w - t0b.w, f, t0b.w) + geb.w;
        __stcs(&orow[lane], va);
        __stcs(&orow[lane + 32], vb);
    } else {
        float4 z = make_float4(0.f, 0.f, 0.f, 0.f);
        __stcs(&orow[lane], z);
        __stcs(&orow[lane + 32], z);
    }
}

extern "C" void kernel_launch(void* const* d_in, const int* in_sizes, int n_in,
                              void* d_out, int out_size) {
    const float* expr     = (const float*)d_in[0];
    const float* gene_emb = (const float*)d_in[1];
    const float* w1       = (const float*)d_in[2];
    const float* b1       = (const float*)d_in[3];
    const float* w2       = (const float*)d_in[4];
    const float* b2       = (const float*)d_in[5];
    const float* cls      = (const float*)d_in[6];
    float* out = (float*)d_out;

    const int D = in_sizes[2];              // 256
    const int G = in_sizes[1] / D;          // 20000
    const int B = in_sizes[0] / G;          // 16

    long Kp1; int hasMask;
    if (out_size % ((long)B * (D + 1)) == 0) {
        Kp1 = out_size / ((long)B * (D + 1));
        hasMask = 1;
    } else {
        Kp1 = out_size / ((long)B * D);
        hasMask = 0;
    }
    const int K = (int)Kp1 - 1;             // 2048
    if (B > MAXB || K > MAXK || D != D_DIM) return;
    if (TOPK_NT * SEG < G) return;
    if (K % 8 != 0) return;

    cudaFuncSetAttribute(fused_kernel,
                         cudaFuncAttributeMaxDynamicSharedMemorySize, DYN_BYTES);

    fused_kernel<<<B + TGM_BLOCKS, TOPK_NT, DYN_BYTES>>>(
        expr, w1, b1, w2, b2, cls, out, B, G, K, hasMask);

    interp_kernel<<<(B * K) / 8, 256>>>(gene_emb, out, B, G, K);
}